// round 16
// baseline (speedup 1.0000x reference)
#include <cuda_runtime.h>

#define NB 32
#define NC 64
#define NP 8192
#define NS 64
#define NK 64
typedef unsigned long long u64;
typedef unsigned int u32;

#define OUT_NF  33554432ll            // node_fea offset in out
#define OUT_NO  33685504ll            // node_offset offset in out

// ---- scratch (device globals; allocations forbidden) ----
__device__ float g_fea_t[(size_t)NB * NP * NC];   // [b][n][c]
__device__ float g_res_t[(size_t)NB * NP * NC];   // [b][n][o]
__device__ float g_fploc[NB * NS * 3];
__device__ int   g_fidx [NB * NS];
__device__ int   g_gidx [NB * NS * NK];
__device__ float g_nodeloc[NB * NS * 3];
__device__ float4 g_t3[(size_t)NB * NP];          // per-point interp weights+idx
__device__ float g_ssum[NC], g_ssq[NC];

// ---- exact-order helpers (block FMA contraction on index-critical math) ----
__device__ __forceinline__ float sq3(float x, float y, float z) {
    return __fadd_rn(__fadd_rn(__fmul_rn(x, x), __fmul_rn(y, y)), __fmul_rn(z, z));
}
__device__ __forceinline__ float dot3(float ax, float ay, float az,
                                      float bx, float by, float bz) {
    return __fadd_rn(__fadd_rn(__fmul_rn(ax, bx), __fmul_rn(ay, by)), __fmul_rn(az, bz));
}
__device__ __forceinline__ float sqd(float aa, float bb, float d) {
    return __fsub_rn(__fadd_rn(aa, bb), __fmul_rn(2.0f, d));
}
__device__ __forceinline__ u32 f2u(float f) {   // monotone float -> uint (handles negatives)
    u32 u = __float_as_uint(f);
    return u ^ ((u32)((int)u >> 31) | 0x80000000u);
}
__device__ __forceinline__ u64 u64min(u64 a, u64 b) { return a < b ? a : b; }
__device__ __forceinline__ u64 u64max(u64 a, u64 b) { return a > b ? a : b; }

// ---- packed f32x2 (Blackwell) : componentwise rn, bit-identical to scalar ----
__device__ __forceinline__ u64 pack2(float lo, float hi) {
    u64 r; asm("mov.b64 %0,{%1,%2};" : "=l"(r) : "f"(lo), "f"(hi)); return r;
}
__device__ __forceinline__ void unpack2(u64 v, float& lo, float& hi) {
    asm("mov.b64 {%0,%1},%2;" : "=f"(lo), "=f"(hi) : "l"(v));
}
__device__ __forceinline__ u64 add2(u64 a, u64 b) {
    u64 r; asm("add.rn.f32x2 %0,%1,%2;" : "=l"(r) : "l"(a), "l"(b)); return r;
}
__device__ __forceinline__ u64 mul2(u64 a, u64 b) {
    u64 r; asm("mul.rn.f32x2 %0,%1,%2;" : "=l"(r) : "l"(a), "l"(b)); return r;
}

// ---------------- k0: zero BN stats ----------------
__global__ void k_zero() {
    int t = threadIdx.x;
    if (t < NC) { g_ssum[t] = 0.f; g_ssq[t] = 0.f; }
}

// ------- kC: fea_t transpose only -------
__global__ void __launch_bounds__(256) k_copy(const float* __restrict__ fea) {
    __shared__ float ft[64 * 68];
    int b = blockIdx.y, n0 = blockIdx.x * 64;
    int tid = threadIdx.x;
    size_t fbase = (size_t)b * NC * NP + n0;
    int p = tid & 63, c4 = tid >> 6;
#pragma unroll
    for (int i = 0; i < 16; i++) {
        int c = i * 4 + c4;
        ft[c * 68 + p] = fea[fbase + (size_t)c * NP + p];
    }
    __syncthreads();
    size_t tbase = ((size_t)b * NP + n0) * 64;
#pragma unroll
    for (int i = 0; i < 16; i++) {
        int idx = i * 256 + tid;
        int pp = idx >> 6, cc = idx & 63;
        g_fea_t[tbase + (size_t)pp * 64 + cc] = ft[cc * 68 + pp];
    }
}

// ------- kO: out[0:64] copy — SM streaming (replaces 32 CE memcpy nodes) -------
__global__ void __launch_bounds__(256) k_outcpy(const float* __restrict__ fea,
                                                float* __restrict__ out) {
    int b = blockIdx.y;
    size_t i = ((size_t)blockIdx.x * 256 + threadIdx.x) * 4;   // within 64*NP
    const float4 v = *(const float4*)(fea + (size_t)b * 64 * NP + i);
    *(float4*)(out + (size_t)b * 128 * NP + i) = v;
}

// ------- k1: res GEMM + BN stats -------
__global__ void __launch_bounds__(256) k_gemm(const float* __restrict__ fea,
                                              const float* __restrict__ W,
                                              const float* __restrict__ bias) {
    __shared__ float ft[64 * 68];
    __shared__ float wt[64 * 68];
    int b = blockIdx.y, n0 = blockIdx.x * 64;
    int tid = threadIdx.x;
#pragma unroll
    for (int i = 0; i < 16; i++) {
        int idx = i * 256 + tid;
        int o = idx >> 6, c = idx & 63;
        wt[c * 68 + o] = W[o * 64 + c];
    }
    size_t fbase = (size_t)b * NC * NP + n0;
    {
        int p = tid & 63, c4 = tid >> 6;
#pragma unroll
        for (int i = 0; i < 16; i++) {
            int c = i * 4 + c4;
            ft[c * 68 + p] = fea[fbase + (size_t)c * NP + p];
        }
    }
    __syncthreads();
    int pi = tid & 15, oi = tid >> 4;
    int p0 = pi * 4, o0 = oi * 4;
    float acc[4][4];
    {
        float b0 = bias[o0], b1 = bias[o0 + 1], b2 = bias[o0 + 2], b3 = bias[o0 + 3];
#pragma unroll
        for (int j = 0; j < 4; j++) { acc[j][0] = b0; acc[j][1] = b1; acc[j][2] = b2; acc[j][3] = b3; }
    }
#pragma unroll 8
    for (int c = 0; c < 64; c++) {
        float4 wv = *(const float4*)&wt[c * 68 + o0];
        float4 fv = *(const float4*)&ft[c * 68 + p0];
        float f[4] = {fv.x, fv.y, fv.z, fv.w};
#pragma unroll
        for (int j = 0; j < 4; j++) {
            acc[j][0] += f[j] * wv.x;
            acc[j][1] += f[j] * wv.y;
            acc[j][2] += f[j] * wv.z;
            acc[j][3] += f[j] * wv.w;
        }
    }
#pragma unroll
    for (int i = 0; i < 4; i++) {
        float s = acc[0][i] + acc[1][i] + acc[2][i] + acc[3][i];
        float q = acc[0][i] * acc[0][i] + acc[1][i] * acc[1][i] +
                  acc[2][i] * acc[2][i] + acc[3][i] * acc[3][i];
#pragma unroll
        for (int off = 8; off; off >>= 1) {
            s += __shfl_down_sync(0xffffffffu, s, off);
            q += __shfl_down_sync(0xffffffffu, q, off);
        }
        if (pi == 0) {
            atomicAdd(&g_ssum[o0 + i], s);
            atomicAdd(&g_ssq[o0 + i], q);
        }
    }
    __syncthreads();
#pragma unroll
    for (int j = 0; j < 4; j++)
#pragma unroll
        for (int k2 = 0; k2 < 4; k2++)
            ft[(p0 + j) * 65 + o0 + k2] = acc[j][k2];
    __syncthreads();
    {
        size_t rbase = ((size_t)b * NP + n0) * 64;
#pragma unroll
        for (int i = 0; i < 16; i++) {
            int idx = i * 256 + tid;
            int pp = idx >> 6, cc = idx & 63;
            g_res_t[rbase + (size_t)pp * 64 + cc] = ft[pp * 65 + cc];
        }
    }
}

// ------- k3: FPS — float-max inner loop, deferred index scan, emits OLD far -------
__global__ void __launch_bounds__(512) k_fps(const float* __restrict__ loc) {
    int b = blockIdx.x, tid = threadIdx.x;
    const float* L = loc + (size_t)b * 3 * NP;
    u64 pX[8], pY[8], pZ[8];
    float dist[16];
#pragma unroll
    for (int q = 0; q < 8; q++) {
        int n0 = tid + (2 * q) * 512, n1 = tid + (2 * q + 1) * 512;
        pX[q] = pack2(L[n0],          L[n1]);
        pY[q] = pack2(L[NP + n0],     L[NP + n1]);
        pZ[q] = pack2(L[2 * NP + n0], L[2 * NP + n1]);
        dist[2 * q] = 1e10f; dist[2 * q + 1] = 1e10f;
    }
    __shared__ u64 s_val[2][16];
    __shared__ int s_fidx[NS];
    int far = 0;                            // current far (emitted BEFORE update)
    float cx = L[0], cy = L[NP], cz = L[2 * NP];
    int lane = tid & 31, wrp = tid >> 5;
    for (int t = 0; t < NS; t++) {
        if (tid == 0) s_fidx[t] = far;      // reference emits the OLD far
        u64 c2x = pack2(-cx, -cx), c2y = pack2(-cy, -cy), c2z = pack2(-cz, -cz);
        float bm = -1.f;                    // running max dist (>= +0 always)
#pragma unroll
        for (int q = 0; q < 8; q++) {
            u64 dx = add2(pX[q], c2x);
            u64 dy = add2(pY[q], c2y);
            u64 dz = add2(pZ[q], c2z);
            u64 s = add2(add2(mul2(dx, dx), mul2(dy, dy)), mul2(dz, dz));
            float lo, hi; unpack2(s, lo, hi);
            float d0 = fminf(dist[2 * q], lo);     dist[2 * q] = d0;
            float d1 = fminf(dist[2 * q + 1], hi); dist[2 * q + 1] = d1;
            bm = fmaxf(bm, fmaxf(d0, d1));
        }
        // dist >= +0 -> raw bits monotone & bit-equality == value-equality
        u32 m = __reduce_max_sync(0xffffffffu, __float_as_uint(bm));
        int mi = 0x7fffffff;
#pragma unroll
        for (int i = 0; i < 16; i++)
            if (__float_as_uint(dist[i]) == m) mi = min(mi, tid + i * 512);
        u32 rmi = __reduce_min_sync(0xffffffffu, (u32)mi);
        if (lane == 0) s_val[t & 1][wrp] = ((u64)m << 32) | (u32)(8191 - (int)rmi);
        __syncthreads();
        u64 w = s_val[t & 1][0];
#pragma unroll
        for (int i = 1; i < 16; i++) w = u64max(w, s_val[t & 1][i]);
        far = 8191 - (int)(w & 0xffffffffull);
        cx = L[far]; cy = L[NP + far]; cz = L[2 * NP + far];  // broadcast, L1-hot
    }
    __syncthreads();
    for (int idx = tid; idx < NS; idx += 512)
        g_fidx[b * NS + idx] = s_fidx[idx];
    for (int idx = tid; idx < NS * 3; idx += 512) {
        int s = idx / 3, r = idx % 3;
        g_fploc[(b * NS + s) * 3 + r] = L[(size_t)r * NP + s_fidx[s]];
    }
}

// ---------------- k4: ball query (first<=64 in-ball indices ascending) ----
__global__ void __launch_bounds__(256) k_qball(const float* __restrict__ loc) {
    int w = blockIdx.x * 8 + (threadIdx.x >> 5);
    int lane = threadIdx.x & 31;
    int b = w >> 6;
    float nx = g_fploc[w * 3], ny = g_fploc[w * 3 + 1], nz = g_fploc[w * 3 + 2];
    float nn = sq3(nx, ny, nz);
    const float* L = loc + (size_t)b * 3 * NP;
    int* gout = g_gidx + w * NK;
    int cnt = 0, first = -1;
    for (int st = 0; st < NP; st += 32) {
        int n = st + lane;
        float x = L[n], y = L[NP + n], z = L[2 * NP + n];
        float sqr = sqd(nn, sq3(x, y, z), dot3(nx, ny, nz, x, y, z));
        bool ok = !(sqr > 0.09f);
        unsigned m = __ballot_sync(0xffffffffu, ok);
        if (first < 0 && m) first = st + __ffs(m) - 1;
        int pos = cnt + __popc(m & ((1u << lane) - 1u));
        if (ok && pos < NK) gout[pos] = n;
        cnt += __popc(m);
        if (cnt >= NK) break;
    }
    if (first < 0) first = 0;
    for (int p = cnt + lane; p < NK; p += 32) gout[p] = first;
}

// ---------------- k5: seman / node_offset / node_loc ----------------
__global__ void __launch_bounds__(64) k_seman(const float* __restrict__ loc,
                                              const float* __restrict__ pred_w,
                                              float* __restrict__ out) {
    int node = blockIdx.x;
    int b = node >> 6, s = node & 63;
    int k = threadIdx.x;
    __shared__ float s_fp[64], s_pw0[64], s_pw1[64], s_pw2[64], s_fl[3], s_red[2][3];
    int fid = g_fidx[node];
    s_fp[k] = g_fea_t[((size_t)b * NP + fid) * 64 + k];
    s_pw0[k] = pred_w[k];
    s_pw1[k] = pred_w[64 + k];
    s_pw2[k] = pred_w[128 + k];
    if (k < 3) s_fl[k] = g_fploc[node * 3 + k];
    __syncthreads();
    int idx = g_gidx[node * 64 + k];
    const float4* fr = (const float4*)(g_fea_t + ((size_t)b * NP + idx) * 64);
    float a0 = 0.f, a1 = 0.f, a2 = 0.f;
#pragma unroll
    for (int q = 0; q < 16; q++) {
        float4 f = fr[q];
        float g0 = f.x - s_fp[q * 4], g1 = f.y - s_fp[q * 4 + 1];
        float g2 = f.z - s_fp[q * 4 + 2], g3 = f.w - s_fp[q * 4 + 3];
        a0 += s_pw0[q * 4] * g0 + s_pw0[q * 4 + 1] * g1 + s_pw0[q * 4 + 2] * g2 + s_pw0[q * 4 + 3] * g3;
        a1 += s_pw1[q * 4] * g0 + s_pw1[q * 4 + 1] * g1 + s_pw1[q * 4 + 2] * g2 + s_pw1[q * 4 + 3] * g3;
        a2 += s_pw2[q * 4] * g0 + s_pw2[q * 4 + 1] * g1 + s_pw2[q * 4 + 2] * g2 + s_pw2[q * 4 + 3] * g3;
    }
    float t0 = tanhf(a0), t1 = tanhf(a1), t2 = tanhf(a2);
    const float* L = loc + (size_t)b * 3 * NP;
    float p0 = t0 * (L[idx] - s_fl[0]);
    float p1 = t1 * (L[NP + idx] - s_fl[1]);
    float p2 = t2 * (L[2 * NP + idx] - s_fl[2]);
#pragma unroll
    for (int off = 16; off; off >>= 1) {
        p0 += __shfl_down_sync(0xffffffffu, p0, off);
        p1 += __shfl_down_sync(0xffffffffu, p1, off);
        p2 += __shfl_down_sync(0xffffffffu, p2, off);
    }
    int lane = k & 31, warp = k >> 5;
    if (lane == 0) { s_red[warp][0] = p0; s_red[warp][1] = p1; s_red[warp][2] = p2; }
    __syncthreads();
    if (k == 0) {
#pragma unroll
        for (int r = 0; r < 3; r++) {
            float off = (s_red[0][r] + s_red[1][r]) * (1.0f / 64.0f);
            out[OUT_NO + b * 192 + r * 64 + s] = off;
            g_nodeloc[node * 3 + r] = s_fl[r] + off;
        }
    }
}

// ----- k6: exact 64-NN + fused BN-finalize + node_fea epilogue -----
__device__ __forceinline__ void knn_build4(const u32* keys, int base,
                                           u64& q0, u64& q1, u64& q2, u64& q3) {
    q0 = q1 = q2 = q3 = ~0ull;
#pragma unroll
    for (int i = 0; i < 32; i++) {
        int n = base + i * 32;
        u64 c = ((u64)keys[n] << 32) | (u32)n;
        if (c < q3) {
            q3 = c;
            if (q3 < q2) { u64 t = q2; q2 = q3; q3 = t; }
            if (q2 < q1) { u64 t = q1; q1 = q2; q2 = t; }
            if (q1 < q0) { u64 t = q0; q0 = q1; q1 = t; }
        }
    }
}

__global__ void __launch_bounds__(256) k_knn(const float* __restrict__ loc,
                                             const float* __restrict__ gamma,
                                             const float* __restrict__ beta,
                                             float* __restrict__ out) {
    __shared__ u32 keys[NP];              // 32 KB; aliased by node_fea stage later
    __shared__ u64 wlist[8][64];
    __shared__ float s2[4][64];
    __shared__ float sA[64], sB[64];
    __shared__ int s_sel[64];
    int node = blockIdx.x, b = node >> 6, sidx = node & 63, t = threadIdx.x;
    int lane = t & 31, w = t >> 5;
    if (t < 64) {                          // fused BN finalize (stats ready: e_bn)
        float cntf = (float)(NB * NP);
        float mean = g_ssum[t] / cntf;
        float var = g_ssq[t] / cntf - mean * mean;
        float A = rsqrtf(var + 1e-5f) * gamma[t];
        sA[t] = A;
        sB[t] = beta[t] - mean * A;
    }
    float nx = g_nodeloc[node * 3], ny = g_nodeloc[node * 3 + 1], nz = g_nodeloc[node * 3 + 2];
    float na = sq3(nx, ny, nz);
    const float* L = loc + (size_t)b * 3 * NP;
#pragma unroll 4
    for (int c = 0; c < 32; c++) {
        int n = c * 256 + t;
        float x = L[n], y = L[NP + n], z = L[2 * NP + n];
        keys[n] = f2u(sqd(na, sq3(x, y, z), dot3(nx, ny, nz, x, y, z)));
    }
    __syncthreads();
    // lane owns points n = w*1024 + i*32 + lane  (conflict-free LDS)
    int base = w * 1024 + lane;
    u64 q0, q1, q2, q3;
    knn_build4(keys, base, q0, q1, q2, q3);
    for (int r = 0; r < NK; r++) {
        u32 hi = (u32)(q0 >> 32), lo = (u32)q0;
        u32 m    = __reduce_min_sync(0xffffffffu, hi);
        u32 widx = __reduce_min_sync(0xffffffffu, (hi == m) ? lo : 0xffffffffu);
        if (lane == 0) wlist[w][r] = ((u64)m << 32) | widx;
        if (hi == m && lo == widx) {
            keys[widx] = 0xffffffffu;
            q0 = q1; q1 = q2; q2 = q3; q3 = ~0ull;
            if (q0 == ~0ull)
                knn_build4(keys, base, q0, q1, q2, q3);
        }
    }
    __syncthreads();
    // parallel rank-based merge of 8 sorted 64-lists (keys unique -> exact set)
    for (int cidx = t; cidx < 512; cidx += 256) {
        int lw = cidx >> 6, li = cidx & 63;
        u64 c = wlist[lw][li];
        int rank = li;
#pragma unroll
        for (int ow = 0; ow < 8; ow++) {
            if (ow == lw) continue;
            int lo2 = 0;
#pragma unroll
            for (int stp = 32; stp; stp >>= 1) {
                int probe = lo2 + stp;
                if (probe <= 64 && wlist[ow][probe - 1] < c) lo2 = probe;
            }
            rank += lo2;
        }
        if (rank < NK) s_sel[rank] = (int)(c & 0xffffffffull);
    }
    __syncthreads();
    // ---- fused node_fea: gather res_t rows of selected set, BN+relu, max ----
    float* s = (float*)keys;              // reuse dead keys smem: [c][k] 64*65
    int c0 = 2 * lane;
    float A0 = sA[c0], A1 = sA[c0 + 1], B0 = sB[c0], B1 = sB[c0 + 1];
#pragma unroll
    for (int r = 0; r < 8; r++) {
        int row = w * 8 + r;
        int idx = s_sel[row];
        float2 v = *(const float2*)(g_res_t + ((size_t)b * NP + idx) * 64 + c0);
        s[c0 * 65 + row]       = fmaxf(fmaf(A0, v.x, B0), 0.f);
        s[(c0 + 1) * 65 + row] = fmaxf(fmaf(A1, v.y, B1), 0.f);
    }
    __syncthreads();
    int ch = t & 63, kq = t >> 6;
    const float* col = &s[ch * 65 + kq * 16];
    float m2 = col[0];
#pragma unroll
    for (int i = 1; i < 16; i++) m2 = fmaxf(m2, col[i]);
    s2[kq][ch] = m2;
    __syncthreads();
    if (t < 64) {
        float v = fmaxf(fmaxf(s2[0][t], s2[1][t]), fmaxf(s2[2][t], s2[3][t]));
        out[OUT_NF + b * 4096 + t * 64 + sidx] = v;
    }
}

// ------- k8a: per-point top-3 nodes + weights (overlaps knn) -------
__global__ void __launch_bounds__(256) k_top3(const float* __restrict__ loc) {
    __shared__ float snx[64], sny[64], snz[64], sbb[64];
    int b = blockIdx.y, t = threadIdx.x;
    int n = blockIdx.x * 256 + t;
    if (t < 64) {
        float x = g_nodeloc[(b * 64 + t) * 3];
        float y = g_nodeloc[(b * 64 + t) * 3 + 1];
        float z = g_nodeloc[(b * 64 + t) * 3 + 2];
        snx[t] = x; sny[t] = y; snz[t] = z;
        sbb[t] = sq3(x, y, z);
    }
    __syncthreads();
    const float* L = loc + (size_t)b * 3 * NP;
    float x = L[n], y = L[NP + n], z = L[2 * NP + n];
    float aa = sq3(x, y, z);
    float d0 = 1e30f, d1 = 1e30f, d2 = 1e30f;
    int i0 = 0, i1 = 0, i2 = 0;
#pragma unroll 8
    for (int k = 0; k < 64; k++) {
        float d = sqd(aa, sbb[k], dot3(x, y, z, snx[k], sny[k], snz[k]));
        if (d < d0)      { d2 = d1; i2 = i1; d1 = d0; i1 = i0; d0 = d; i0 = k; }
        else if (d < d1) { d2 = d1; i2 = i1; d1 = d; i1 = k; }
        else if (d < d2) { d2 = d; i2 = k; }
    }
    d0 = fmaxf(d0, 1e-10f); d1 = fmaxf(d1, 1e-10f); d2 = fmaxf(d2, 1e-10f);
    float w0 = 1.0f / d0, w1 = 1.0f / d1, w2 = 1.0f / d2;
    float ws = (w0 + w1) + w2;
    w0 /= ws; w1 /= ws; w2 /= ws;
    u32 bits = (u32)i0 | ((u32)i1 << 8) | ((u32)i2 << 16);
    g_t3[(size_t)b * NP + n] = make_float4(w0, w1, w2, __uint_as_float(bits));
}

// ------- k8b: gather + weighted sum + output stream -------
__global__ void __launch_bounds__(256) k_interp(float* __restrict__ out) {
    __shared__ float s_nf[64 * 65];   // [node][ch] padded
    int b = blockIdx.y, t = threadIdx.x;
    int n = blockIdx.x * 256 + t;
    const float* nfsrc = out + OUT_NF + (size_t)b * 4096;
#pragma unroll
    for (int i = 0; i < 16; i++) {
        int idx = i * 256 + t;
        int o = idx >> 6, s = idx & 63;
        s_nf[s * 65 + o] = nfsrc[idx];
    }
    __syncthreads();
    float4 v = g_t3[(size_t)b * NP + n];
    u32 bits = __float_as_uint(v.w);
    const float* f0 = &s_nf[(bits & 255u) * 65];
    const float* f1 = &s_nf[((bits >> 8) & 255u) * 65];
    const float* f2 = &s_nf[((bits >> 16) & 255u) * 65];
    size_t obase = (size_t)b * 128 * NP + (size_t)64 * NP + n;
#pragma unroll 8
    for (int c = 0; c < 64; c++) {
        float r = f0[c] * v.x + f1[c] * v.y + f2[c] * v.z;
        out[obase + (size_t)c * NP] = r;
    }
}

extern "C" void kernel_launch(void* const* d_in, const int* in_sizes, int n_in,
                              void* d_out, int out_size) {
    const float* fea    = (const float*)d_in[0];
    const float* loc    = (const float*)d_in[1];
    const float* pred_w = (const float*)d_in[2];
    const float* res_w  = (const float*)d_in[3];
    const float* res_b  = (const float*)d_in[4];
    const float* gamma  = (const float*)d_in[5];
    const float* beta   = (const float*)d_in[6];
    float* out = (float*)d_out;

    static cudaStream_t s_side = 0, s_copy = 0;
    static cudaEvent_t  e_fork = 0, e_copy = 0, e_sem = 0, e_side = 0, e_t3 = 0, e_bn = 0;
    if (!s_side) {
        cudaStreamCreateWithFlags(&s_side, cudaStreamNonBlocking);
        cudaStreamCreateWithFlags(&s_copy, cudaStreamNonBlocking);
        cudaEventCreateWithFlags(&e_fork, cudaEventDisableTiming);
        cudaEventCreateWithFlags(&e_copy, cudaEventDisableTiming);
        cudaEventCreateWithFlags(&e_sem,  cudaEventDisableTiming);
        cudaEventCreateWithFlags(&e_side, cudaEventDisableTiming);
        cudaEventCreateWithFlags(&e_t3,   cudaEventDisableTiming);
        cudaEventCreateWithFlags(&e_bn,   cudaEventDisableTiming);
    }

    // fork
    cudaEventRecord(e_fork, 0);
    cudaStreamWaitEvent(s_side, e_fork, 0);
    cudaStreamWaitEvent(s_copy, e_fork, 0);

    // copy branch: fea_t transpose + out[0:64] SM copy (replaces CE memcpys)
    k_copy  <<<dim3(128, NB), 256, 0, s_copy>>>(fea);
    cudaEventRecord(e_copy, s_copy);
    k_outcpy<<<dim3(NP * 64 / 1024, NB), 256, 0, s_copy>>>(fea, out);

    // main branch: GEMM chain (off critical path); BN finalize fused into knn
    k_zero <<<1, 64>>>();
    k_gemm <<<dim3(128, NB), 256>>>(fea, res_w, res_b);
    cudaEventRecord(e_bn, 0);

    // side branch: loc-chain up to fused knn+nodefea
    k_fps  <<<NB, 512, 0, s_side>>>(loc);
    k_qball<<<NB * NS / 8, 256, 0, s_side>>>(loc);
    cudaStreamWaitEvent(s_side, e_copy, 0);
    k_seman<<<NB * NS, 64, 0, s_side>>>(loc, pred_w, out);
    cudaEventRecord(e_sem, s_side);
    cudaStreamWaitEvent(s_side, e_bn, 0);
    k_knn  <<<NB * NS, 256, 0, s_side>>>(loc, gamma, beta, out);
    cudaEventRecord(e_side, s_side);

    // top3 branch: overlaps knn (needs only nodeloc)
    cudaStreamWaitEvent(s_copy, e_sem, 0);
    k_top3<<<dim3(NP / 256, NB), 256, 0, s_copy>>>(loc);
    cudaEventRecord(e_t3, s_copy);

    // join
    cudaStreamWaitEvent(0, e_side, 0);
    cudaStreamWaitEvent(0, e_t3, 0);
    k_interp <<<dim3(NP / 256, NB), 256>>>(out);
}

// round 17
// speedup vs baseline: 1.0944x; 1.0944x over previous
#include <cuda_runtime.h>

#define NB 32
#define NC 64
#define NP 8192
#define NS 64
#define NK 64
typedef unsigned long long u64;
typedef unsigned int u32;

#define OUT_NF  33554432ll            // node_fea offset in out
#define OUT_NO  33685504ll            // node_offset offset in out

// ---- scratch (device globals; allocations forbidden) ----
__device__ float g_fea_t[(size_t)NB * NP * NC];   // [b][n][c]
__device__ float g_res_t[(size_t)NB * NP * NC];   // [b][n][o]
__device__ float g_fploc[NB * NS * 3];
__device__ int   g_fidx [NB * NS];
__device__ int   g_gidx [NB * NS * NK];
__device__ float g_nodeloc[NB * NS * 3];
__device__ float4 g_t3[(size_t)NB * NP];          // per-point interp weights+idx
__device__ float g_ssum[NC], g_ssq[NC];

// ---- exact-order helpers (block FMA contraction on index-critical math) ----
__device__ __forceinline__ float sq3(float x, float y, float z) {
    return __fadd_rn(__fadd_rn(__fmul_rn(x, x), __fmul_rn(y, y)), __fmul_rn(z, z));
}
__device__ __forceinline__ float dot3(float ax, float ay, float az,
                                      float bx, float by, float bz) {
    return __fadd_rn(__fadd_rn(__fmul_rn(ax, bx), __fmul_rn(ay, by)), __fmul_rn(az, bz));
}
__device__ __forceinline__ float sqd(float aa, float bb, float d) {
    return __fsub_rn(__fadd_rn(aa, bb), __fmul_rn(2.0f, d));
}
__device__ __forceinline__ u32 f2u(float f) {   // monotone float -> uint (handles negatives)
    u32 u = __float_as_uint(f);
    return u ^ ((u32)((int)u >> 31) | 0x80000000u);
}
__device__ __forceinline__ u64 u64min(u64 a, u64 b) { return a < b ? a : b; }
__device__ __forceinline__ u64 u64max(u64 a, u64 b) { return a > b ? a : b; }

// ---- packed f32x2 (Blackwell) : componentwise rn, bit-identical to scalar ----
__device__ __forceinline__ u64 pack2(float lo, float hi) {
    u64 r; asm("mov.b64 %0,{%1,%2};" : "=l"(r) : "f"(lo), "f"(hi)); return r;
}
__device__ __forceinline__ void unpack2(u64 v, float& lo, float& hi) {
    asm("mov.b64 {%0,%1},%2;" : "=f"(lo), "=f"(hi) : "l"(v));
}
__device__ __forceinline__ u64 add2(u64 a, u64 b) {
    u64 r; asm("add.rn.f32x2 %0,%1,%2;" : "=l"(r) : "l"(a), "l"(b)); return r;
}
__device__ __forceinline__ u64 mul2(u64 a, u64 b) {
    u64 r; asm("mul.rn.f32x2 %0,%1,%2;" : "=l"(r) : "l"(a), "l"(b)); return r;
}

// ---------------- k0: zero BN stats ----------------
__global__ void k_zero() {
    int t = threadIdx.x;
    if (t < NC) { g_ssum[t] = 0.f; g_ssq[t] = 0.f; }
}

// ------- k1: res GEMM + fea_t transpose + BN stats (k_copy fused back in) -------
__global__ void __launch_bounds__(256) k_gemm(const float* __restrict__ fea,
                                              const float* __restrict__ W,
                                              const float* __restrict__ bias) {
    __shared__ float ft[64 * 68];
    __shared__ float wt[64 * 68];
    int b = blockIdx.y, n0 = blockIdx.x * 64;
    int tid = threadIdx.x;
#pragma unroll
    for (int i = 0; i < 16; i++) {
        int idx = i * 256 + tid;
        int o = idx >> 6, c = idx & 63;
        wt[c * 68 + o] = W[o * 64 + c];
    }
    size_t fbase = (size_t)b * NC * NP + n0;
    {
        int p = tid & 63, c4 = tid >> 6;
#pragma unroll
        for (int i = 0; i < 16; i++) {
            int c = i * 4 + c4;
            ft[c * 68 + p] = fea[fbase + (size_t)c * NP + p];
        }
    }
    __syncthreads();
    // fea_t transpose writeout (fused; reuses the staged tile)
    {
        size_t tbase = ((size_t)b * NP + n0) * 64;
#pragma unroll
        for (int i = 0; i < 16; i++) {
            int idx = i * 256 + tid;
            int pp = idx >> 6, cc = idx & 63;
            g_fea_t[tbase + (size_t)pp * 64 + cc] = ft[cc * 68 + pp];
        }
    }
    int pi = tid & 15, oi = tid >> 4;
    int p0 = pi * 4, o0 = oi * 4;
    float acc[4][4];
    {
        float b0 = bias[o0], b1 = bias[o0 + 1], b2 = bias[o0 + 2], b3 = bias[o0 + 3];
#pragma unroll
        for (int j = 0; j < 4; j++) { acc[j][0] = b0; acc[j][1] = b1; acc[j][2] = b2; acc[j][3] = b3; }
    }
#pragma unroll 8
    for (int c = 0; c < 64; c++) {
        float4 wv = *(const float4*)&wt[c * 68 + o0];
        float4 fv = *(const float4*)&ft[c * 68 + p0];
        float f[4] = {fv.x, fv.y, fv.z, fv.w};
#pragma unroll
        for (int j = 0; j < 4; j++) {
            acc[j][0] += f[j] * wv.x;
            acc[j][1] += f[j] * wv.y;
            acc[j][2] += f[j] * wv.z;
            acc[j][3] += f[j] * wv.w;
        }
    }
#pragma unroll
    for (int i = 0; i < 4; i++) {
        float s = acc[0][i] + acc[1][i] + acc[2][i] + acc[3][i];
        float q = acc[0][i] * acc[0][i] + acc[1][i] * acc[1][i] +
                  acc[2][i] * acc[2][i] + acc[3][i] * acc[3][i];
#pragma unroll
        for (int off = 8; off; off >>= 1) {
            s += __shfl_down_sync(0xffffffffu, s, off);
            q += __shfl_down_sync(0xffffffffu, q, off);
        }
        if (pi == 0) {
            atomicAdd(&g_ssum[o0 + i], s);
            atomicAdd(&g_ssq[o0 + i], q);
        }
    }
    __syncthreads();
#pragma unroll
    for (int j = 0; j < 4; j++)
#pragma unroll
        for (int k2 = 0; k2 < 4; k2++)
            ft[(p0 + j) * 65 + o0 + k2] = acc[j][k2];
    __syncthreads();
    {
        size_t rbase = ((size_t)b * NP + n0) * 64;
#pragma unroll
        for (int i = 0; i < 16; i++) {
            int idx = i * 256 + tid;
            int pp = idx >> 6, cc = idx & 63;
            g_res_t[rbase + (size_t)pp * 64 + cc] = ft[pp * 65 + cc];
        }
    }
}

// ------- k3: FPS — float-max inner loop, deferred index scan, emits OLD far -------
__global__ void __launch_bounds__(512) k_fps(const float* __restrict__ loc) {
    int b = blockIdx.x, tid = threadIdx.x;
    const float* L = loc + (size_t)b * 3 * NP;
    u64 pX[8], pY[8], pZ[8];
    float dist[16];
#pragma unroll
    for (int q = 0; q < 8; q++) {
        int n0 = tid + (2 * q) * 512, n1 = tid + (2 * q + 1) * 512;
        pX[q] = pack2(L[n0],          L[n1]);
        pY[q] = pack2(L[NP + n0],     L[NP + n1]);
        pZ[q] = pack2(L[2 * NP + n0], L[2 * NP + n1]);
        dist[2 * q] = 1e10f; dist[2 * q + 1] = 1e10f;
    }
    __shared__ u64 s_val[2][16];
    __shared__ int s_fidx[NS];
    int far = 0;                            // current far (emitted BEFORE update)
    float cx = L[0], cy = L[NP], cz = L[2 * NP];
    int lane = tid & 31, wrp = tid >> 5;
    for (int t = 0; t < NS; t++) {
        if (tid == 0) s_fidx[t] = far;      // reference emits the OLD far
        u64 c2x = pack2(-cx, -cx), c2y = pack2(-cy, -cy), c2z = pack2(-cz, -cz);
        float bm = -1.f;                    // running max dist (>= +0 always)
#pragma unroll
        for (int q = 0; q < 8; q++) {
            u64 dx = add2(pX[q], c2x);
            u64 dy = add2(pY[q], c2y);
            u64 dz = add2(pZ[q], c2z);
            u64 s = add2(add2(mul2(dx, dx), mul2(dy, dy)), mul2(dz, dz));
            float lo, hi; unpack2(s, lo, hi);
            float d0 = fminf(dist[2 * q], lo);     dist[2 * q] = d0;
            float d1 = fminf(dist[2 * q + 1], hi); dist[2 * q + 1] = d1;
            bm = fmaxf(bm, fmaxf(d0, d1));
        }
        // dist >= +0 -> raw bits monotone & bit-equality == value-equality
        u32 m = __reduce_max_sync(0xffffffffu, __float_as_uint(bm));
        int mi = 0x7fffffff;
#pragma unroll
        for (int i = 0; i < 16; i++)
            if (__float_as_uint(dist[i]) == m) mi = min(mi, tid + i * 512);
        u32 rmi = __reduce_min_sync(0xffffffffu, (u32)mi);
        if (lane == 0) s_val[t & 1][wrp] = ((u64)m << 32) | (u32)(8191 - (int)rmi);
        __syncthreads();
        u64 w = s_val[t & 1][0];
#pragma unroll
        for (int i = 1; i < 16; i++) w = u64max(w, s_val[t & 1][i]);
        far = 8191 - (int)(w & 0xffffffffull);
        cx = L[far]; cy = L[NP + far]; cz = L[2 * NP + far];  // broadcast, L1-hot
    }
    __syncthreads();
    for (int idx = tid; idx < NS; idx += 512)
        g_fidx[b * NS + idx] = s_fidx[idx];
    for (int idx = tid; idx < NS * 3; idx += 512) {
        int s = idx / 3, r = idx % 3;
        g_fploc[(b * NS + s) * 3 + r] = L[(size_t)r * NP + s_fidx[s]];
    }
}

// ---------------- k4: ball query (first<=64 in-ball indices ascending) ----
__global__ void __launch_bounds__(256) k_qball(const float* __restrict__ loc) {
    int w = blockIdx.x * 8 + (threadIdx.x >> 5);
    int lane = threadIdx.x & 31;
    int b = w >> 6;
    float nx = g_fploc[w * 3], ny = g_fploc[w * 3 + 1], nz = g_fploc[w * 3 + 2];
    float nn = sq3(nx, ny, nz);
    const float* L = loc + (size_t)b * 3 * NP;
    int* gout = g_gidx + w * NK;
    int cnt = 0, first = -1;
    for (int st = 0; st < NP; st += 32) {
        int n = st + lane;
        float x = L[n], y = L[NP + n], z = L[2 * NP + n];
        float sqr = sqd(nn, sq3(x, y, z), dot3(nx, ny, nz, x, y, z));
        bool ok = !(sqr > 0.09f);
        unsigned m = __ballot_sync(0xffffffffu, ok);
        if (first < 0 && m) first = st + __ffs(m) - 1;
        int pos = cnt + __popc(m & ((1u << lane) - 1u));
        if (ok && pos < NK) gout[pos] = n;
        cnt += __popc(m);
        if (cnt >= NK) break;
    }
    if (first < 0) first = 0;
    for (int p = cnt + lane; p < NK; p += 32) gout[p] = first;
}

// ---------------- k5: seman / node_offset / node_loc ----------------
__global__ void __launch_bounds__(64) k_seman(const float* __restrict__ loc,
                                              const float* __restrict__ pred_w,
                                              float* __restrict__ out) {
    int node = blockIdx.x;
    int b = node >> 6, s = node & 63;
    int k = threadIdx.x;
    __shared__ float s_fp[64], s_pw0[64], s_pw1[64], s_pw2[64], s_fl[3], s_red[2][3];
    int fid = g_fidx[node];
    s_fp[k] = g_fea_t[((size_t)b * NP + fid) * 64 + k];
    s_pw0[k] = pred_w[k];
    s_pw1[k] = pred_w[64 + k];
    s_pw2[k] = pred_w[128 + k];
    if (k < 3) s_fl[k] = g_fploc[node * 3 + k];
    __syncthreads();
    int idx = g_gidx[node * 64 + k];
    const float4* fr = (const float4*)(g_fea_t + ((size_t)b * NP + idx) * 64);
    float a0 = 0.f, a1 = 0.f, a2 = 0.f;
#pragma unroll
    for (int q = 0; q < 16; q++) {
        float4 f = fr[q];
        float g0 = f.x - s_fp[q * 4], g1 = f.y - s_fp[q * 4 + 1];
        float g2 = f.z - s_fp[q * 4 + 2], g3 = f.w - s_fp[q * 4 + 3];
        a0 += s_pw0[q * 4] * g0 + s_pw0[q * 4 + 1] * g1 + s_pw0[q * 4 + 2] * g2 + s_pw0[q * 4 + 3] * g3;
        a1 += s_pw1[q * 4] * g0 + s_pw1[q * 4 + 1] * g1 + s_pw1[q * 4 + 2] * g2 + s_pw1[q * 4 + 3] * g3;
        a2 += s_pw2[q * 4] * g0 + s_pw2[q * 4 + 1] * g1 + s_pw2[q * 4 + 2] * g2 + s_pw2[q * 4 + 3] * g3;
    }
    float t0 = tanhf(a0), t1 = tanhf(a1), t2 = tanhf(a2);
    const float* L = loc + (size_t)b * 3 * NP;
    float p0 = t0 * (L[idx] - s_fl[0]);
    float p1 = t1 * (L[NP + idx] - s_fl[1]);
    float p2 = t2 * (L[2 * NP + idx] - s_fl[2]);
#pragma unroll
    for (int off = 16; off; off >>= 1) {
        p0 += __shfl_down_sync(0xffffffffu, p0, off);
        p1 += __shfl_down_sync(0xffffffffu, p1, off);
        p2 += __shfl_down_sync(0xffffffffu, p2, off);
    }
    int lane = k & 31, warp = k >> 5;
    if (lane == 0) { s_red[warp][0] = p0; s_red[warp][1] = p1; s_red[warp][2] = p2; }
    __syncthreads();
    if (k == 0) {
#pragma unroll
        for (int r = 0; r < 3; r++) {
            float off = (s_red[0][r] + s_red[1][r]) * (1.0f / 64.0f);
            out[OUT_NO + b * 192 + r * 64 + s] = off;
            g_nodeloc[node * 3 + r] = s_fl[r] + off;
        }
    }
}

// ----- k6: exact 64-NN + fused BN-finalize + node_fea epilogue -----
__device__ __forceinline__ void knn_build4(const u32* keys, int base,
                                           u64& q0, u64& q1, u64& q2, u64& q3) {
    q0 = q1 = q2 = q3 = ~0ull;
#pragma unroll
    for (int i = 0; i < 32; i++) {
        int n = base + i * 32;
        u64 c = ((u64)keys[n] << 32) | (u32)n;
        if (c < q3) {
            q3 = c;
            if (q3 < q2) { u64 t = q2; q2 = q3; q3 = t; }
            if (q2 < q1) { u64 t = q1; q1 = q2; q2 = t; }
            if (q1 < q0) { u64 t = q0; q0 = q1; q1 = t; }
        }
    }
}

__global__ void __launch_bounds__(256) k_knn(const float* __restrict__ loc,
                                             const float* __restrict__ gamma,
                                             const float* __restrict__ beta,
                                             float* __restrict__ out) {
    __shared__ u32 keys[NP];              // 32 KB; aliased by node_fea stage later
    __shared__ u64 wlist[8][64];
    __shared__ float s2[4][64];
    __shared__ float sA[64], sB[64];
    __shared__ int s_sel[64];
    int node = blockIdx.x, b = node >> 6, sidx = node & 63, t = threadIdx.x;
    int lane = t & 31, w = t >> 5;
    if (t < 64) {                          // fused BN finalize (stats ready: e_bn)
        float cntf = (float)(NB * NP);
        float mean = g_ssum[t] / cntf;
        float var = g_ssq[t] / cntf - mean * mean;
        float A = rsqrtf(var + 1e-5f) * gamma[t];
        sA[t] = A;
        sB[t] = beta[t] - mean * A;
    }
    float nx = g_nodeloc[node * 3], ny = g_nodeloc[node * 3 + 1], nz = g_nodeloc[node * 3 + 2];
    float na = sq3(nx, ny, nz);
    const float* L = loc + (size_t)b * 3 * NP;
#pragma unroll 4
    for (int c = 0; c < 32; c++) {
        int n = c * 256 + t;
        float x = L[n], y = L[NP + n], z = L[2 * NP + n];
        keys[n] = f2u(sqd(na, sq3(x, y, z), dot3(nx, ny, nz, x, y, z)));
    }
    __syncthreads();
    // lane owns points n = w*1024 + i*32 + lane  (conflict-free LDS)
    int base = w * 1024 + lane;
    u64 q0, q1, q2, q3;
    knn_build4(keys, base, q0, q1, q2, q3);
    for (int r = 0; r < NK; r++) {
        u32 hi = (u32)(q0 >> 32), lo = (u32)q0;
        u32 m    = __reduce_min_sync(0xffffffffu, hi);
        u32 widx = __reduce_min_sync(0xffffffffu, (hi == m) ? lo : 0xffffffffu);
        if (lane == 0) wlist[w][r] = ((u64)m << 32) | widx;
        if (hi == m && lo == widx) {
            keys[widx] = 0xffffffffu;
            q0 = q1; q1 = q2; q2 = q3; q3 = ~0ull;
            if (q0 == ~0ull)
                knn_build4(keys, base, q0, q1, q2, q3);
        }
    }
    __syncthreads();
    // parallel rank-based merge of 8 sorted 64-lists (keys unique -> exact set)
    for (int cidx = t; cidx < 512; cidx += 256) {
        int lw = cidx >> 6, li = cidx & 63;
        u64 c = wlist[lw][li];
        int rank = li;
#pragma unroll
        for (int ow = 0; ow < 8; ow++) {
            if (ow == lw) continue;
            int lo2 = 0;
#pragma unroll
            for (int stp = 32; stp; stp >>= 1) {
                int probe = lo2 + stp;
                if (probe <= 64 && wlist[ow][probe - 1] < c) lo2 = probe;
            }
            rank += lo2;
        }
        if (rank < NK) s_sel[rank] = (int)(c & 0xffffffffull);
    }
    __syncthreads();
    // ---- fused node_fea: gather res_t rows of selected set, BN+relu, max ----
    float* s = (float*)keys;              // reuse dead keys smem: [c][k] 64*65
    int c0 = 2 * lane;
    float A0 = sA[c0], A1 = sA[c0 + 1], B0 = sB[c0], B1 = sB[c0 + 1];
#pragma unroll
    for (int r = 0; r < 8; r++) {
        int row = w * 8 + r;
        int idx = s_sel[row];
        float2 v = *(const float2*)(g_res_t + ((size_t)b * NP + idx) * 64 + c0);
        s[c0 * 65 + row]       = fmaxf(fmaf(A0, v.x, B0), 0.f);
        s[(c0 + 1) * 65 + row] = fmaxf(fmaf(A1, v.y, B1), 0.f);
    }
    __syncthreads();
    int ch = t & 63, kq = t >> 6;
    const float* col = &s[ch * 65 + kq * 16];
    float m2 = col[0];
#pragma unroll
    for (int i = 1; i < 16; i++) m2 = fmaxf(m2, col[i]);
    s2[kq][ch] = m2;
    __syncthreads();
    if (t < 64) {
        float v = fmaxf(fmaxf(s2[0][t], s2[1][t]), fmaxf(s2[2][t], s2[3][t]));
        out[OUT_NF + b * 4096 + t * 64 + sidx] = v;
    }
}

// ------- k8a: per-point top-3 nodes + weights (overlaps knn) -------
__global__ void __launch_bounds__(256) k_top3(const float* __restrict__ loc) {
    __shared__ float snx[64], sny[64], snz[64], sbb[64];
    int b = blockIdx.y, t = threadIdx.x;
    int n = blockIdx.x * 256 + t;
    if (t < 64) {
        float x = g_nodeloc[(b * 64 + t) * 3];
        float y = g_nodeloc[(b * 64 + t) * 3 + 1];
        float z = g_nodeloc[(b * 64 + t) * 3 + 2];
        snx[t] = x; sny[t] = y; snz[t] = z;
        sbb[t] = sq3(x, y, z);
    }
    __syncthreads();
    const float* L = loc + (size_t)b * 3 * NP;
    float x = L[n], y = L[NP + n], z = L[2 * NP + n];
    float aa = sq3(x, y, z);
    float d0 = 1e30f, d1 = 1e30f, d2 = 1e30f;
    int i0 = 0, i1 = 0, i2 = 0;
#pragma unroll 8
    for (int k = 0; k < 64; k++) {
        float d = sqd(aa, sbb[k], dot3(x, y, z, snx[k], sny[k], snz[k]));
        if (d < d0)      { d2 = d1; i2 = i1; d1 = d0; i1 = i0; d0 = d; i0 = k; }
        else if (d < d1) { d2 = d1; i2 = i1; d1 = d; i1 = k; }
        else if (d < d2) { d2 = d; i2 = k; }
    }
    d0 = fmaxf(d0, 1e-10f); d1 = fmaxf(d1, 1e-10f); d2 = fmaxf(d2, 1e-10f);
    float w0 = 1.0f / d0, w1 = 1.0f / d1, w2 = 1.0f / d2;
    float ws = (w0 + w1) + w2;
    w0 /= ws; w1 /= ws; w2 /= ws;
    u32 bits = (u32)i0 | ((u32)i1 << 8) | ((u32)i2 << 16);
    g_t3[(size_t)b * NP + n] = make_float4(w0, w1, w2, __uint_as_float(bits));
}

// ------- k8b: gather + weighted sum + output stream -------
__global__ void __launch_bounds__(256) k_interp(float* __restrict__ out) {
    __shared__ float s_nf[64 * 65];   // [node][ch] padded
    int b = blockIdx.y, t = threadIdx.x;
    int n = blockIdx.x * 256 + t;
    const float* nfsrc = out + OUT_NF + (size_t)b * 4096;
#pragma unroll
    for (int i = 0; i < 16; i++) {
        int idx = i * 256 + t;
        int o = idx >> 6, s = idx & 63;
        s_nf[s * 65 + o] = nfsrc[idx];
    }
    __syncthreads();
    float4 v = g_t3[(size_t)b * NP + n];
    u32 bits = __float_as_uint(v.w);
    const float* f0 = &s_nf[(bits & 255u) * 65];
    const float* f1 = &s_nf[((bits >> 8) & 255u) * 65];
    const float* f2 = &s_nf[((bits >> 16) & 255u) * 65];
    size_t obase = (size_t)b * 128 * NP + (size_t)64 * NP + n;
#pragma unroll 8
    for (int c = 0; c < 64; c++) {
        float r = f0[c] * v.x + f1[c] * v.y + f2[c] * v.z;
        out[obase + (size_t)c * NP] = r;
    }
}

extern "C" void kernel_launch(void* const* d_in, const int* in_sizes, int n_in,
                              void* d_out, int out_size) {
    const float* fea    = (const float*)d_in[0];
    const float* loc    = (const float*)d_in[1];
    const float* pred_w = (const float*)d_in[2];
    const float* res_w  = (const float*)d_in[3];
    const float* res_b  = (const float*)d_in[4];
    const float* gamma  = (const float*)d_in[5];
    const float* beta   = (const float*)d_in[6];
    float* out = (float*)d_out;

    static cudaStream_t s_side = 0, s_copy = 0;
    static cudaEvent_t  e_fork = 0, e_sem = 0, e_side = 0, e_t3 = 0, e_bn = 0;
    if (!s_side) {
        cudaStreamCreateWithFlags(&s_side, cudaStreamNonBlocking);
        cudaStreamCreateWithFlags(&s_copy, cudaStreamNonBlocking);
        cudaEventCreateWithFlags(&e_fork, cudaEventDisableTiming);
        cudaEventCreateWithFlags(&e_sem,  cudaEventDisableTiming);
        cudaEventCreateWithFlags(&e_side, cudaEventDisableTiming);
        cudaEventCreateWithFlags(&e_t3,   cudaEventDisableTiming);
        cudaEventCreateWithFlags(&e_bn,   cudaEventDisableTiming);
    }

    // fork
    cudaEventRecord(e_fork, 0);
    cudaStreamWaitEvent(s_side, e_fork, 0);
    cudaStreamWaitEvent(s_copy, e_fork, 0);

    // copy branch: out[0:64] copy (copy engine, contiguous)
    for (int b = 0; b < NB; b++)
        cudaMemcpyAsync(out + (size_t)b * 128 * NP, fea + (size_t)b * 64 * NP,
                        (size_t)64 * NP * sizeof(float),
                        cudaMemcpyDeviceToDevice, s_copy);

    // main branch: GEMM (+fea_t transpose) chain; BN finalize fused into knn
    k_zero <<<1, 64>>>();
    k_gemm <<<dim3(128, NB), 256>>>(fea, res_w, res_b);
    cudaEventRecord(e_bn, 0);

    // side branch: loc-chain up to fused knn+nodefea
    k_fps  <<<NB, 512, 0, s_side>>>(loc);
    k_qball<<<NB * NS / 8, 256, 0, s_side>>>(loc);
    cudaStreamWaitEvent(s_side, e_bn, 0);      // fea_t + stats ready
    k_seman<<<NB * NS, 64, 0, s_side>>>(loc, pred_w, out);
    cudaEventRecord(e_sem, s_side);
    k_knn  <<<NB * NS, 256, 0, s_side>>>(loc, gamma, beta, out);
    cudaEventRecord(e_side, s_side);

    // top3 branch: overlaps knn (needs only nodeloc)
    cudaStreamWaitEvent(s_copy, e_sem, 0);
    k_top3<<<dim3(NP / 256, NB), 256, 0, s_copy>>>(loc);
    cudaEventRecord(e_t3, s_copy);

    // join
    cudaStreamWaitEvent(0, e_side, 0);
    cudaStreamWaitEvent(0, e_t3, 0);
    k_interp <<<dim3(NP / 256, NB), 256>>>(out);
}